// round 8
// baseline (speedup 1.0000x reference)
#include <cuda_runtime.h>
#include <stdint.h>

#define B_IMGS    64
#define HW        384
#define IMG_ELEMS (HW * HW)
#define N_TOTAL   (B_IMGS * IMG_ELEMS)
#define PAD       3
#define N_OUT     (64.0 * 378.0 * 378.0)

#define TW        64
#define TH        32
#define IN_W      70
#define AOS_STRIDE 71   // float4 units; conflict-free
#define GX_TILES  6
#define GY_TILES  12
#define NTILES_TOTAL (GX_TILES * GY_TILES * B_IMGS)   // 4608

#define PBLOCKS   888        // 148 SMs * 6 CTAs -> one resident wave
#define MAX_BLOCKS 256

__device__ double       g_sum;
__device__ unsigned int g_ticket;
__device__ float        g_blockmax[MAX_BLOCKS];

// ---------------------------------------------------------------------------
__global__ __launch_bounds__(256)
void prep_kernel(const float* __restrict__ gt) {
    if (blockIdx.x == 0 && threadIdx.x == 0) { g_sum = 0.0; g_ticket = 0u; }

    const float4* v = reinterpret_cast<const float4*>(gt);
    const int n4 = N_TOTAL / 4;
    float m = 0.0f;
    for (int i = blockIdx.x * 256 + threadIdx.x; i < n4; i += MAX_BLOCKS * 256) {
        float4 x = v[i];
        m = fmaxf(m, fmaxf(fmaxf(x.x, x.y), fmaxf(x.z, x.w)));
    }
    #pragma unroll
    for (int o = 16; o; o >>= 1) m = fmaxf(m, __shfl_xor_sync(0xffffffffu, m, o));
    __shared__ float smax[8];
    int lane = threadIdx.x & 31, wid = threadIdx.x >> 5;
    if (lane == 0) smax[wid] = m;
    __syncthreads();
    if (wid == 0) {
        m = (lane < 8) ? smax[lane] : 0.0f;
        #pragma unroll
        for (int o = 4; o; o >>= 1) m = fmaxf(m, __shfl_xor_sync(0xffffffffu, m, o));
        if (lane == 0) g_blockmax[blockIdx.x] = m;
    }
}

// ---------------------------------------------------------------------------
// Phase A: vertical 7-row box sums of (a, b, a^2+b^2, ab); 3 row-chunks x 70
// columns (210 threads), rolling 7-row register window.
template <bool EDGE>
__device__ __forceinline__ void phaseA(
    const float* __restrict__ gbase, const float* __restrict__ pbase,
    int bx, int by, int tid, float4* aos)
{
    if (tid >= 3 * IN_W) return;
    const int row0  = by * TH;
    const int chunk = tid / IN_W;               // 0..2
    const int c     = tid - chunk * IN_W;       // 0..69
    const int o0    = chunk * 11;
    const int nout  = (chunk == 2) ? 10 : 11;

    float g[7], p[7];
    float s0 = 0.f, s1 = 0.f, s23 = 0.f, s4 = 0.f;

    if (!EDGE) {
        const float* gp = gbase + (row0 + o0) * HW + (bx * TW + c);
        const float* pp = pbase + (row0 + o0) * HW + (bx * TW + c);
        #pragma unroll
        for (int i = 0; i < 6; i++) {
            float a = __ldg(gp); float b = __ldg(pp);
            gp += HW; pp += HW;
            g[i] = a; p[i] = b;
            s0 += a; s1 += b;
            s23 = fmaf(a, a, s23); s23 = fmaf(b, b, s23);
            s4  = fmaf(a, b, s4);
        }
        #pragma unroll
        for (int j = 0; j < 11; j++) {
            int slot = (6 + j) % 7;
            float a = __ldg(gp); float b = __ldg(pp);
            gp += HW; pp += HW;
            g[slot] = a; p[slot] = b;
            s0 += a; s1 += b;
            s23 = fmaf(a, a, s23); s23 = fmaf(b, b, s23);
            s4  = fmaf(a, b, s4);
            if (j < nout)
                aos[(o0 + j) * AOS_STRIDE + c] = make_float4(s0, s1, s23, s4);
            int os = j % 7;
            float ga = g[os], pa = p[os];
            s0 -= ga; s1 -= pa;
            s23 -= fmaf(ga, ga, pa * pa);
            s4  -= ga * pa;
        }
    } else {
        const int gx = min(bx * TW + c, HW - 1);
        const float* gp = gbase + gx;
        const float* pp = pbase + gx;
        const int rb = row0 + o0;
        #pragma unroll
        for (int i = 0; i < 6; i++) {
            int gy = min(rb + i, HW - 1);
            float a = __ldg(gp + gy * HW); float b = __ldg(pp + gy * HW);
            g[i] = a; p[i] = b;
            s0 += a; s1 += b;
            s23 = fmaf(a, a, s23); s23 = fmaf(b, b, s23);
            s4  = fmaf(a, b, s4);
        }
        #pragma unroll
        for (int j = 0; j < 11; j++) {
            int slot = (6 + j) % 7;
            int gy = min(rb + 6 + j, HW - 1);
            float a = __ldg(gp + gy * HW); float b = __ldg(pp + gy * HW);
            g[slot] = a; p[slot] = b;
            s0 += a; s1 += b;
            s23 = fmaf(a, a, s23); s23 = fmaf(b, b, s23);
            s4  = fmaf(a, b, s4);
            if (j < nout)
                aos[(o0 + j) * AOS_STRIDE + c] = make_float4(s0, s1, s23, s4);
            int os = j % 7;
            float ga = g[os], pa = p[os];
            s0 -= ga; s1 -= pa;
            s23 -= fmaf(ga, ga, pa * pa);
            s4  -= ga * pa;
        }
    }
}

// Phase B: horizontal rolling 7-sum over smem + strength-reduced SSIM.
// Constants: C1q=C1*49^2, C2q=C2*49^2, K1=2401/24, K2=49/24, K3=2401/48, K4=49/48.
template <bool EDGE>
__device__ __forceinline__ float phaseB(
    const float4* aos, int bx, int by, int tid,
    float C1q, float C2q)
{
    const float K1 = 2401.0f / 24.0f;
    const float K2 = 49.0f   / 24.0f;
    const float K3 = 2401.0f / 48.0f;
    const float K4 = 49.0f   / 48.0f;

    const int seg = tid >> 5;
    const int row = tid & 31;
    const int c0  = seg * 8;
    const int abase = row * AOS_STRIDE + c0;

    const bool rowvalid = EDGE ? ((PAD + by * TH + row) <= HW - 1 - PAD) : true;
    const int ox0 = PAD + bx * TW + c0;

    float4 s = make_float4(0.f, 0.f, 0.f, 0.f);
    #pragma unroll
    for (int i = 0; i < 6; i++) {
        float4 v = aos[abase + i];
        s.x += v.x; s.y += v.y; s.z += v.z; s.w += v.w;
    }

    float local = 0.0f;
    #pragma unroll
    for (int k = 0; k < 8; k++) {
        float4 v = aos[abase + 6 + k];
        s.x += v.x; s.y += v.y; s.z += v.z; s.w += v.w;

        bool valid = EDGE ? (rowvalid && (ox0 + k) <= HW - 1 - PAD) : true;
        if (valid) {
            float t_ab = s.x * s.y;                      // A*B
            float t_sq = fmaf(s.x, s.x, s.y * s.y);      // A^2+B^2
            float f1 = fmaf(2.0f, t_ab, C1q);
            float f2 = fmaf(K1, s.w, fmaf(-K2, t_ab, C2q));
            float f3 = t_sq + C1q;
            float f4 = fmaf(K3, s.z, fmaf(-K4, t_sq, C2q));
            local += __fdividef(f1 * f2, f3 * f4);
        }

        float4 w = aos[abase + k];
        s.x -= w.x; s.y -= w.y; s.z -= w.z; s.w -= w.w;
    }
    return local;
}

// ---------------------------------------------------------------------------
__global__ __launch_bounds__(256, 6)
void ssim_kernel(const float* __restrict__ gt, const float* __restrict__ pred,
                 float* __restrict__ out) {
    __shared__ float4 aos[TH * AOS_STRIDE];
    __shared__ float  sred[8];
    __shared__ float  smaxv;

    const int tid = threadIdx.x;

    // one-time: finish global max reduction (warp 0)
    if (tid < 32) {
        float m = 0.0f;
        #pragma unroll
        for (int i = 0; i < MAX_BLOCKS / 32; i++)
            m = fmaxf(m, g_blockmax[tid + 32 * i]);
        #pragma unroll
        for (int o = 16; o; o >>= 1) m = fmaxf(m, __shfl_xor_sync(0xffffffffu, m, o));
        if (tid == 0) smaxv = m;
    }
    __syncthreads();

    const float R   = smaxv;
    const float C1q = (0.01f * R) * (0.01f * R) * 2401.0f;
    const float C2q = (0.03f * R) * (0.03f * R) * 2401.0f;

    float acc = 0.0f;

    for (int idx = blockIdx.x; idx < NTILES_TOTAL; idx += PBLOCKS) {
        const int img = idx / (GX_TILES * GY_TILES);
        const int r   = idx - img * (GX_TILES * GY_TILES);
        const int by  = r / GX_TILES;
        const int bx  = r - by * GX_TILES;

        const float* gbase = gt   + img * IMG_ELEMS;
        const float* pbase = pred + img * IMG_ELEMS;

        __syncthreads();    // aos safe to overwrite (prev tile's phase B done)

        if (bx < GX_TILES - 1 && by < GY_TILES - 1) {
            phaseA<false>(gbase, pbase, bx, by, tid, aos);
            __syncthreads();
            acc += phaseB<false>(aos, bx, by, tid, C1q, C2q);
        } else {
            phaseA<true>(gbase, pbase, bx, by, tid, aos);
            __syncthreads();
            acc += phaseB<true>(aos, bx, by, tid, C1q, C2q);
        }
    }

    // block reduce + global accumulate + last-block finalize
    #pragma unroll
    for (int o = 16; o; o >>= 1) acc += __shfl_xor_sync(0xffffffffu, acc, o);
    if ((tid & 31) == 0) sred[tid >> 5] = acc;
    __syncthreads();
    if (tid == 0) {
        float v = sred[0] + sred[1] + sred[2] + sred[3]
                + sred[4] + sred[5] + sred[6] + sred[7];
        atomicAdd(&g_sum, (double)v);
        __threadfence();
        unsigned t = atomicAdd(&g_ticket, 1u);
        if (t == PBLOCKS - 1) {
            double total = atomicAdd(&g_sum, 0.0);
            out[0] = (float)(total / N_OUT);
        }
    }
}

// ---------------------------------------------------------------------------
extern "C" void kernel_launch(void* const* d_in, const int* in_sizes, int n_in,
                              void* d_out, int out_size) {
    const float* gt   = (const float*)d_in[0];
    const float* pred = (const float*)d_in[1];
    float* out = (float*)d_out;

    prep_kernel<<<MAX_BLOCKS, 256>>>(gt);
    ssim_kernel<<<PBLOCKS, 256>>>(gt, pred, out);
}

// round 9
// speedup vs baseline: 1.0888x; 1.0888x over previous
#include <cuda_runtime.h>
#include <stdint.h>

#define B_IMGS    64
#define HW        384
#define IMG_ELEMS (HW * HW)
#define N_TOTAL   (B_IMGS * IMG_ELEMS)
#define PAD       3
#define N_OUT     (64.0 * 378.0 * 378.0)

#define TW        64
#define TH        32
#define IN_W      70
#define AOS_STRIDE 71   // float4 units; conflict-free
#define GX_TILES  6
#define GY_TILES  12
#define NBLOCKS   (GX_TILES * GY_TILES * B_IMGS)   // 4608

#define MAX_BLOCKS 256

__device__ double       g_sum;
__device__ unsigned int g_ticket;
__device__ float        g_blockmax[MAX_BLOCKS];

// ---------------------------------------------------------------------------
__global__ __launch_bounds__(256)
void prep_kernel(const float* __restrict__ gt) {
    if (blockIdx.x == 0 && threadIdx.x == 0) { g_sum = 0.0; g_ticket = 0u; }

    const float4* v = reinterpret_cast<const float4*>(gt);
    const int n4 = N_TOTAL / 4;
    float m = 0.0f;
    for (int i = blockIdx.x * 256 + threadIdx.x; i < n4; i += MAX_BLOCKS * 256) {
        float4 x = v[i];
        m = fmaxf(m, fmaxf(fmaxf(x.x, x.y), fmaxf(x.z, x.w)));
    }
    #pragma unroll
    for (int o = 16; o; o >>= 1) m = fmaxf(m, __shfl_xor_sync(0xffffffffu, m, o));
    __shared__ float smax[8];
    int lane = threadIdx.x & 31, wid = threadIdx.x >> 5;
    if (lane == 0) smax[wid] = m;
    __syncthreads();
    if (wid == 0) {
        m = (lane < 8) ? smax[lane] : 0.0f;
        #pragma unroll
        for (int o = 4; o; o >>= 1) m = fmaxf(m, __shfl_xor_sync(0xffffffffu, m, o));
        if (lane == 0) g_blockmax[blockIdx.x] = m;
    }
}

// ---------------------------------------------------------------------------
// Phase A: vertical 7-row box sums of (a, b, a^2+b^2, ab); 3 row-chunks x 70
// columns (210 threads), rolling 7-row window. Warp 7 finishes global max.
// Phase B: horizontal rolling 7-sum + strength-reduced SSIM (49^2-scaled).
template <bool EDGE>
__device__ __forceinline__ void tile_work(
    const float* __restrict__ gbase, const float* __restrict__ pbase,
    int bx, int by, int tid,
    float4* aos, float* smaxv_p, float* local_out)
{
    const int row0 = by * TH;
    // ---- Phase A ----
    if (tid < 3 * IN_W) {
        const int chunk = tid / IN_W;               // 0..2
        const int c     = tid - chunk * IN_W;       // 0..69
        const int o0    = chunk * 11;
        const int nout  = (chunk == 2) ? 10 : 11;

        float g[7], p[7];
        float s0 = 0.f, s1 = 0.f, s23 = 0.f, s4 = 0.f;

        if (!EDGE) {
            const float* gp = gbase + (row0 + o0) * HW + (bx * TW + c);
            const float* pp = pbase + (row0 + o0) * HW + (bx * TW + c);
            #pragma unroll
            for (int i = 0; i < 6; i++) {
                float a = __ldg(gp); float b = __ldg(pp);
                gp += HW; pp += HW;
                g[i] = a; p[i] = b;
                s0 += a; s1 += b;
                s23 = fmaf(a, a, s23); s23 = fmaf(b, b, s23);
                s4  = fmaf(a, b, s4);
            }
            #pragma unroll
            for (int j = 0; j < 11; j++) {
                int slot = (6 + j) % 7;
                float a = __ldg(gp); float b = __ldg(pp);
                gp += HW; pp += HW;
                g[slot] = a; p[slot] = b;
                s0 += a; s1 += b;
                s23 = fmaf(a, a, s23); s23 = fmaf(b, b, s23);
                s4  = fmaf(a, b, s4);
                if (j < nout)
                    aos[(o0 + j) * AOS_STRIDE + c] = make_float4(s0, s1, s23, s4);
                int os = j % 7;
                float ga = g[os], pa = p[os];
                s0 -= ga; s1 -= pa;
                s23 -= fmaf(ga, ga, pa * pa);
                s4  -= ga * pa;
            }
        } else {
            const int gx = min(bx * TW + c, HW - 1);
            const float* gp = gbase + gx;
            const float* pp = pbase + gx;
            const int rb = row0 + o0;
            #pragma unroll
            for (int i = 0; i < 6; i++) {
                int gy = min(rb + i, HW - 1);
                float a = __ldg(gp + gy * HW); float b = __ldg(pp + gy * HW);
                g[i] = a; p[i] = b;
                s0 += a; s1 += b;
                s23 = fmaf(a, a, s23); s23 = fmaf(b, b, s23);
                s4  = fmaf(a, b, s4);
            }
            #pragma unroll
            for (int j = 0; j < 11; j++) {
                int slot = (6 + j) % 7;
                int gy = min(rb + 6 + j, HW - 1);
                float a = __ldg(gp + gy * HW); float b = __ldg(pp + gy * HW);
                g[slot] = a; p[slot] = b;
                s0 += a; s1 += b;
                s23 = fmaf(a, a, s23); s23 = fmaf(b, b, s23);
                s4  = fmaf(a, b, s4);
                if (j < nout)
                    aos[(o0 + j) * AOS_STRIDE + c] = make_float4(s0, s1, s23, s4);
                int os = j % 7;
                float ga = g[os], pa = p[os];
                s0 -= ga; s1 -= pa;
                s23 -= fmaf(ga, ga, pa * pa);
                s4  -= ga * pa;
            }
        }
    } else if (tid >= 224) {
        int lane = tid - 224;
        float m = 0.0f;
        #pragma unroll
        for (int i = 0; i < MAX_BLOCKS / 32; i++)
            m = fmaxf(m, g_blockmax[lane + 32 * i]);
        #pragma unroll
        for (int o = 16; o; o >>= 1) m = fmaxf(m, __shfl_xor_sync(0xffffffffu, m, o));
        if (lane == 0) *smaxv_p = m;
    }
    __syncthreads();

    // ---- Phase B ----
    const float R   = *smaxv_p;
    const float C1q = (0.01f * R) * (0.01f * R) * 2401.0f;
    const float C2q = (0.03f * R) * (0.03f * R) * 2401.0f;
    const float K1 = 2401.0f / 24.0f;
    const float K2 = 49.0f   / 24.0f;
    const float K3 = 2401.0f / 48.0f;
    const float K4 = 49.0f   / 48.0f;

    const int seg = tid >> 5;
    const int row = tid & 31;
    const int c0  = seg * 8;
    const int abase = row * AOS_STRIDE + c0;

    const bool rowvalid = EDGE ? ((PAD + by * TH + row) <= HW - 1 - PAD) : true;
    const int ox0 = PAD + bx * TW + c0;

    float4 s = make_float4(0.f, 0.f, 0.f, 0.f);
    #pragma unroll
    for (int i = 0; i < 6; i++) {
        float4 v = aos[abase + i];
        s.x += v.x; s.y += v.y; s.z += v.z; s.w += v.w;
    }

    float local = 0.0f;
    #pragma unroll
    for (int k = 0; k < 8; k++) {
        float4 v = aos[abase + 6 + k];
        s.x += v.x; s.y += v.y; s.z += v.z; s.w += v.w;

        bool valid = EDGE ? (rowvalid && (ox0 + k) <= HW - 1 - PAD) : true;
        if (valid) {
            float t_ab = s.x * s.y;                      // A*B
            float t_sq = fmaf(s.x, s.x, s.y * s.y);      // A^2+B^2
            float f1 = fmaf(2.0f, t_ab, C1q);
            float f2 = fmaf(K1, s.w, fmaf(-K2, t_ab, C2q));
            float f3 = t_sq + C1q;
            float f4 = fmaf(K3, s.z, fmaf(-K4, t_sq, C2q));
            local += __fdividef(f1 * f2, f3 * f4);
        }

        float4 w = aos[abase + k];       // re-read subtract operand
        s.x -= w.x; s.y -= w.y; s.z -= w.z; s.w -= w.w;
    }
    *local_out = local;
}

__global__ __launch_bounds__(256, 6)
void ssim_kernel(const float* __restrict__ gt, const float* __restrict__ pred,
                 float* __restrict__ out) {
    __shared__ float4 aos[TH * AOS_STRIDE];
    __shared__ float  sred[8];
    __shared__ float  smaxv;

    const int tid = threadIdx.x;
    const int bx = blockIdx.x, by = blockIdx.y, img = blockIdx.z;

    const float* gbase = gt   + img * IMG_ELEMS;
    const float* pbase = pred + img * IMG_ELEMS;

    float local;
    if (bx < GX_TILES - 1 && by < GY_TILES - 1)
        tile_work<false>(gbase, pbase, bx, by, tid, aos, &smaxv, &local);
    else
        tile_work<true >(gbase, pbase, bx, by, tid, aos, &smaxv, &local);

    #pragma unroll
    for (int o = 16; o; o >>= 1) local += __shfl_xor_sync(0xffffffffu, local, o);
    if ((tid & 31) == 0) sred[tid >> 5] = local;
    __syncthreads();
    if (tid == 0) {
        float v = sred[0] + sred[1] + sred[2] + sred[3]
                + sred[4] + sred[5] + sred[6] + sred[7];
        atomicAdd(&g_sum, (double)v);
        __threadfence();
        unsigned t = atomicAdd(&g_ticket, 1u);
        if (t == NBLOCKS - 1) {
            double total = atomicAdd(&g_sum, 0.0);
            out[0] = (float)(total / N_OUT);
        }
    }
}

// ---------------------------------------------------------------------------
extern "C" void kernel_launch(void* const* d_in, const int* in_sizes, int n_in,
                              void* d_out, int out_size) {
    const float* gt   = (const float*)d_in[0];
    const float* pred = (const float*)d_in[1];
    float* out = (float*)d_out;

    prep_kernel<<<MAX_BLOCKS, 256>>>(gt);
    dim3 grid(GX_TILES, GY_TILES, B_IMGS);
    ssim_kernel<<<grid, 256>>>(gt, pred, out);
}